// round 8
// baseline (speedup 1.0000x reference)
#include <cuda_runtime.h>
#include <stdint.h>

#define BB 256
#define TT 32768
#define TT4 (TT / 4)
#define KK 3
#define ALPHA 0.95f
#define THETA 0.05f
#define LCH 256          // chunk length
#define NCH (TT / LCH)   // 128 chunks
#define WMAX 512         // max warmup steps
#define G 4              // float4 groups (4 steps each) in flight per plane
#define PD 8             // L2 prefetch distance in groups (32 steps)

// scratch: u in blocked transpose [k][t/4][b][4] + pad covering the register
// pipeline's worst-case overrun (last chunk reads ~67 groups past TT4; pad=128 groups)
__device__ float g_uB[KK * TT4 * BB * 4 + 131072];

// ---------------------------------------------------------------------------
// Kernel 1: causal convs. Tile = 32 b x 64 t, 256 threads, 8 outputs/thread.
// Writes u to d_out [b][k][t] and to g_uB [k][t/4][b][4] (both coalesced).
// FMA accumulation order identical to validated R3-R7 kernels (bit-identical u).
// ---------------------------------------------------------------------------
__global__ void __launch_bounds__(256) conv_kernel(const float* __restrict__ x,
                                                   const float* __restrict__ w8,
                                                   const float* __restrict__ w16,
                                                   const float* __restrict__ w32,
                                                   float* __restrict__ u_out) {
    __shared__ float wf[64];   // flipped weights: [0:32)=w32, [32:48)=w16, [48:56)=w8
    __shared__ __align__(16) float buf[KK * 32 * 69];
    float (*xs)[97]     = reinterpret_cast<float (*)[97]>(buf);      // 32 x 97
    float (*us)[32][69] = reinterpret_cast<float (*)[32][69]>(buf);  // 3 x 32 x 69

    const int tid    = threadIdx.x;
    const int w      = tid >> 5;
    const int l      = tid & 31;
    const int tile_t = blockIdx.x * 64;
    const int b0     = blockIdx.y * 32;

    if (tid < 32)       wf[tid] = w32[31 - tid];
    else if (tid < 48)  wf[tid] = w16[47 - tid];
    else if (tid < 56)  wf[tid] = w8[55 - tid];

    // phase A: xs[r][c] = x[b0+r][tile_t-32+c], c in [0,96)
#pragma unroll
    for (int rr = 0; rr < 4; rr++) {
        int r = w + rr * 8;
        const float* xr = x + (size_t)(b0 + r) * TT + tile_t - 32;
#pragma unroll
        for (int cc = 0; cc < 3; cc++) {
            int c = cc * 32 + l;
            xs[r][c] = (tile_t - 32 + c >= 0) ? xr[c] : 0.0f;
        }
    }
    __syncthreads();

    // phase B: 8 outputs per thread
    const int bl = l;
    const int tq = w * 8;
    float win[39];
#pragma unroll
    for (int i = 0; i < 39; i++) win[i] = xs[bl][tq + 1 + i];
    __syncthreads();   // xs dead; union reused as us

    float a32[8] = {0,0,0,0,0,0,0,0}, a16[8] = {0,0,0,0,0,0,0,0}, a8[8] = {0,0,0,0,0,0,0,0};
#pragma unroll
    for (int d = 0; d < 32; d++) {
        float wv = wf[d];
#pragma unroll
        for (int j = 0; j < 8; j++) a32[j] = fmaf(wv, win[31 + j - d], a32[j]);
    }
#pragma unroll
    for (int d = 0; d < 16; d++) {
        float wv = wf[32 + d];
#pragma unroll
        for (int j = 0; j < 8; j++) a16[j] = fmaf(wv, win[31 + j - d], a16[j]);
    }
#pragma unroll
    for (int d = 0; d < 8; d++) {
        float wv = wf[48 + d];
#pragma unroll
        for (int j = 0; j < 8; j++) a8[j] = fmaf(wv, win[31 + j - d], a8[j]);
    }
#pragma unroll
    for (int j = 0; j < 8; j++) {
        us[0][bl][tq + j] = a8[j];
        us[1][bl][tq + j] = a16[j];
        us[2][bl][tq + j] = a32[j];
    }
    __syncthreads();

    // phase D: u_out [b][k][t] (warp writes 128B rows)
#pragma unroll
    for (int bbq = 0; bbq < 4; bbq++) {
        int bb = w * 4 + bbq;
        float* orow = u_out + (size_t)(b0 + bb) * 3 * TT + tile_t;
#pragma unroll
        for (int k = 0; k < 3; k++)
#pragma unroll
            for (int h = 0; h < 2; h++)
                orow[(size_t)k * TT + 32 * h + l] = us[k][bb][32 * h + l];
    }
    // phase E: g_uB [k][tg][b][4] (lane = b, warp writes 512B chunks)
#pragma unroll
    for (int r = 0; r < 6; r++) {
        int row = w + r * 8;          // 0..47 = k*16 + tgl
        int k   = row >> 4;
        int tgl = row & 15;
        float4 v;
        v.x = us[k][l][tgl * 4 + 0];
        v.y = us[k][l][tgl * 4 + 1];
        v.z = us[k][l][tgl * 4 + 2];
        v.w = us[k][l][tgl * 4 + 3];
        *(float4*)&g_uB[(((size_t)k * TT4 + (tile_t >> 2) + tgl) * BB + b0 + l) * 4] = v;
    }
}

// ---------------------------------------------------------------------------
// Kernel 2: chunked WTA-LIF scan + fused spike expansion. Reads g_uB (warp =
// 512B coalesced). Register pipeline (G groups) + L2 prefetch PD ahead.
// Spikes packed thread-locally (no ballots): 32-step windows, compile-time
// bit positions, 3 words/thread/window to smem; expansion at block end.
// ---------------------------------------------------------------------------
__device__ __forceinline__ void lif_step(float& v0, float& v1, float& v2,
                                         float u0, float u1, float u2,
                                         bool& s0, bool& s1, bool& s2) {
    v0 = fmaf(ALPHA, v0, u0);
    v1 = fmaf(ALPHA, v1, u1);
    v2 = fmaf(ALPHA, v2, u2);
    // winner-take-all, argmax first-index tie-break, spike iff winner >= theta
    // (pure FSETP-AND chain; bitwise-identical to the fmax/THETA_M form)
    s0 = (v0 >= v1) & (v0 >= v2) & (v0 >= THETA);
    s1 = (v1 >  v0) & (v1 >= v2) & (v1 >= THETA);
    s2 = (v2 >  v0) & (v2 >  v1) & (v2 >= THETA);
    v0 = s0 ? v0 - THETA : v0;
    v1 = s1 ? v1 - THETA : v1;
    v2 = s2 ? v2 - THETA : v2;
}

__device__ __forceinline__ void l2pf(const float4* p) {
    asm volatile("prefetch.global.L2 [%0];" :: "l"(p));
}

__global__ void __launch_bounds__(128, 1) scan_kernel(float* __restrict__ out_s) {
    __shared__ uint32_t sb[KK][LCH / 32][128];   // per-thread masks [k][window][b], 12 KB

    const int tid    = threadIdx.x;
    const int b0s    = (blockIdx.x & 1) * 128;
    const int c      = blockIdx.x >> 1;
    const int b      = b0s + tid;
    const int out_t0 = c * LCH;
    const int t0     = (out_t0 > WMAX) ? (out_t0 - WMAX) : 0;
    const int nw     = out_t0 - t0;      // warmup steps (0, 256, or 512)
    const int gb0    = t0 >> 2;          // starting group index

    // plane pointers in float4 units; group stride = BB float4s (4 KB)
    const float4* p0 = (const float4*)g_uB + ((size_t)0 * TT4 + gb0) * BB + b;
    const float4* p1 = (const float4*)g_uB + ((size_t)1 * TT4 + gb0) * BB + b;
    const float4* p2 = (const float4*)g_uB + ((size_t)2 * TT4 + gb0) * BB + b;

    float4 q0[G], q1[G], q2[G];
#pragma unroll
    for (int i = 0; i < G; i++) {
        q0[i] = __ldg(p0 + (size_t)i * BB);
        q1[i] = __ldg(p1 + (size_t)i * BB);
        q2[i] = __ldg(p2 + (size_t)i * BB);
    }
#pragma unroll
    for (int i = G; i < PD; i++) {
        l2pf(p0 + (size_t)i * BB);
        l2pf(p1 + (size_t)i * BB);
        l2pf(p2 + (size_t)i * BB);
    }

    float v0 = 0.f, v1 = 0.f, v2 = 0.f;
    bool s0, s1, s2;

    // ---- warmup ----
    const int ngw = nw >> 2;
#pragma unroll 4
    for (int g = 0; g < ngw; g++) {
        int s = g & (G - 1);
        float4 a = q0[s], bq = q1[s], cq = q2[s];
        q0[s] = __ldg(p0 + (size_t)(g + G) * BB);
        q1[s] = __ldg(p1 + (size_t)(g + G) * BB);
        q2[s] = __ldg(p2 + (size_t)(g + G) * BB);
        l2pf(p0 + (size_t)(g + PD) * BB);
        l2pf(p1 + (size_t)(g + PD) * BB);
        l2pf(p2 + (size_t)(g + PD) * BB);
        lif_step(v0, v1, v2, a.x, bq.x, cq.x, s0, s1, s2);
        lif_step(v0, v1, v2, a.y, bq.y, cq.y, s0, s1, s2);
        lif_step(v0, v1, v2, a.z, bq.z, cq.z, s0, s1, s2);
        lif_step(v0, v1, v2, a.w, bq.w, cq.w, s0, s1, s2);
    }
    p0 += (size_t)ngw * BB; p1 += (size_t)ngw * BB; p2 += (size_t)ngw * BB;

    // ---- main: 8 windows of 32 steps; thread-local bit packing ----
    for (int w32 = 0; w32 < LCH / 32; w32++) {
        uint32_t m0 = 0, m1 = 0, m2 = 0;
#pragma unroll
        for (int gg = 0; gg < 8; gg++) {
            const int g = w32 * 8 + gg;
            const int s = gg & (G - 1);
            float4 a = q0[s], bq = q1[s], cq = q2[s];
            q0[s] = __ldg(p0 + (size_t)(g + G) * BB);
            q1[s] = __ldg(p1 + (size_t)(g + G) * BB);
            q2[s] = __ldg(p2 + (size_t)(g + G) * BB);
            l2pf(p0 + (size_t)(g + PD) * BB);
            l2pf(p1 + (size_t)(g + PD) * BB);
            l2pf(p2 + (size_t)(g + PD) * BB);
#pragma unroll
            for (int j = 0; j < 4; j++) {
                float u0 = (j == 0) ? a.x  : (j == 1) ? a.y  : (j == 2) ? a.z  : a.w;
                float u1 = (j == 0) ? bq.x : (j == 1) ? bq.y : (j == 2) ? bq.z : bq.w;
                float u2 = (j == 0) ? cq.x : (j == 1) ? cq.y : (j == 2) ? cq.z : cq.w;
                lif_step(v0, v1, v2, u0, u1, u2, s0, s1, s2);
                const uint32_t bit = 1u << (gg * 4 + j);
                if (s0) m0 |= bit;
                if (s1) m1 |= bit;
                if (s2) m2 |= bit;
            }
        }
        sb[0][w32][tid] = m0;
        sb[1][w32][tid] = m1;
        sb[2][w32][tid] = m2;
    }
    __syncthreads();

    // ---- fused expansion: 128 b x 3 k x 256 t floats for this block ----
    for (int f = tid; f < 128 * 3 * (LCH / 4); f += 128) {
        int t4 = f & (LCH / 4 - 1);
        int r  = f >> 6;
        int bq = r / 3;
        int k  = r - bq * 3;
        uint32_t wv = sb[k][t4 >> 3][bq];
        int sh = (t4 & 7) * 4;
        float4 o;
        o.x = (float)((wv >> (sh + 0)) & 1u);
        o.y = (float)((wv >> (sh + 1)) & 1u);
        o.z = (float)((wv >> (sh + 2)) & 1u);
        o.w = (float)((wv >> (sh + 3)) & 1u);
        *(float4*)(out_s + ((size_t)(b0s + bq) * 3 + k) * TT + out_t0 + t4 * 4) = o;
    }
}

// ---------------------------------------------------------------------------
extern "C" void kernel_launch(void* const* d_in, const int* in_sizes, int n_in,
                              void* d_out, int out_size) {
    const float* x   = (const float*)d_in[0];
    // d_in[1] = y, unused by the reference outputs
    const float* w8  = (const float*)d_in[2];
    const float* w16 = (const float*)d_in[3];
    const float* w32 = (const float*)d_in[4];
    float* out = (float*)d_out;

    conv_kernel<<<dim3(TT / 64, BB / 32), 256>>>(x, w8, w16, w32, out);
    scan_kernel<<<NCH * 2, 128>>>(out + (size_t)BB * KK * TT);
}

// round 9
// speedup vs baseline: 1.0358x; 1.0358x over previous
#include <cuda_runtime.h>
#include <stdint.h>

#define BB 256
#define TT 32768
#define TT4 (TT / 4)
#define KK 3
#define ALPHA 0.95f
#define THETA 0.05f
#define LCH 256          // chunk length
#define NCH (TT / LCH)   // 128 chunks
#define WMAX 512         // max warmup steps
#define G 8              // float4 groups (4 steps each) in flight per plane

// scratch: u in blocked transpose [k][t/4][b][4] + pad covering the register
// pipeline's worst-case overrun (last chunk reads ~71 groups past TT4; pad=128 groups)
__device__ float g_uB[KK * TT4 * BB * 4 + 131072];

// ---------------------------------------------------------------------------
// Kernel 1: causal convs. Tile = 32 b x 64 t, 256 threads, 8 outputs/thread.
// Writes u to d_out [b][k][t] and to g_uB [k][t/4][b][4] (both coalesced).
// FMA accumulation order identical to validated R3-R8 kernels (bit-identical u).
// ---------------------------------------------------------------------------
__global__ void __launch_bounds__(256) conv_kernel(const float* __restrict__ x,
                                                   const float* __restrict__ w8,
                                                   const float* __restrict__ w16,
                                                   const float* __restrict__ w32,
                                                   float* __restrict__ u_out) {
    __shared__ float wf[64];   // flipped weights: [0:32)=w32, [32:48)=w16, [48:56)=w8
    __shared__ __align__(16) float buf[KK * 32 * 69];
    float (*xs)[97]     = reinterpret_cast<float (*)[97]>(buf);      // 32 x 97
    float (*us)[32][69] = reinterpret_cast<float (*)[32][69]>(buf);  // 3 x 32 x 69

    const int tid    = threadIdx.x;
    const int w      = tid >> 5;
    const int l      = tid & 31;
    const int tile_t = blockIdx.x * 64;
    const int b0     = blockIdx.y * 32;

    if (tid < 32)       wf[tid] = w32[31 - tid];
    else if (tid < 48)  wf[tid] = w16[47 - tid];
    else if (tid < 56)  wf[tid] = w8[55 - tid];

    // phase A: xs[r][c] = x[b0+r][tile_t-32+c], c in [0,96)
#pragma unroll
    for (int rr = 0; rr < 4; rr++) {
        int r = w + rr * 8;
        const float* xr = x + (size_t)(b0 + r) * TT + tile_t - 32;
#pragma unroll
        for (int cc = 0; cc < 3; cc++) {
            int c = cc * 32 + l;
            xs[r][c] = (tile_t - 32 + c >= 0) ? xr[c] : 0.0f;
        }
    }
    __syncthreads();

    // phase B: 8 outputs per thread
    const int bl = l;
    const int tq = w * 8;
    float win[39];
#pragma unroll
    for (int i = 0; i < 39; i++) win[i] = xs[bl][tq + 1 + i];
    __syncthreads();   // xs dead; union reused as us

    float a32[8] = {0,0,0,0,0,0,0,0}, a16[8] = {0,0,0,0,0,0,0,0}, a8[8] = {0,0,0,0,0,0,0,0};
#pragma unroll
    for (int d = 0; d < 32; d++) {
        float wv = wf[d];
#pragma unroll
        for (int j = 0; j < 8; j++) a32[j] = fmaf(wv, win[31 + j - d], a32[j]);
    }
#pragma unroll
    for (int d = 0; d < 16; d++) {
        float wv = wf[32 + d];
#pragma unroll
        for (int j = 0; j < 8; j++) a16[j] = fmaf(wv, win[31 + j - d], a16[j]);
    }
#pragma unroll
    for (int d = 0; d < 8; d++) {
        float wv = wf[48 + d];
#pragma unroll
        for (int j = 0; j < 8; j++) a8[j] = fmaf(wv, win[31 + j - d], a8[j]);
    }
#pragma unroll
    for (int j = 0; j < 8; j++) {
        us[0][bl][tq + j] = a8[j];
        us[1][bl][tq + j] = a16[j];
        us[2][bl][tq + j] = a32[j];
    }
    __syncthreads();

    // phase D: u_out [b][k][t] (warp writes 128B rows)
#pragma unroll
    for (int bbq = 0; bbq < 4; bbq++) {
        int bb = w * 4 + bbq;
        float* orow = u_out + (size_t)(b0 + bb) * 3 * TT + tile_t;
#pragma unroll
        for (int k = 0; k < 3; k++)
#pragma unroll
            for (int h = 0; h < 2; h++)
                orow[(size_t)k * TT + 32 * h + l] = us[k][bb][32 * h + l];
    }
    // phase E: g_uB [k][tg][b][4] (lane = b, warp writes 512B chunks)
#pragma unroll
    for (int r = 0; r < 6; r++) {
        int row = w + r * 8;          // 0..47 = k*16 + tgl
        int k   = row >> 4;
        int tgl = row & 15;
        float4 v;
        v.x = us[k][l][tgl * 4 + 0];
        v.y = us[k][l][tgl * 4 + 1];
        v.z = us[k][l][tgl * 4 + 2];
        v.w = us[k][l][tgl * 4 + 3];
        *(float4*)&g_uB[(((size_t)k * TT4 + (tile_t >> 2) + tgl) * BB + b0 + l) * 4] = v;
    }
}

// ---------------------------------------------------------------------------
// Kernel 2: chunked WTA-LIF scan + fused spike expansion. Reads g_uB (warp =
// 512B coalesced). Deep register pipeline: G=8 groups (32 steps, ~700+ cyc)
// per plane covers DRAM latency directly; no L2 prefetch instructions.
// Windows of 32 steps fully unrolled -> queue index and bit positions are
// compile-time; pointers advance once per window.
// ---------------------------------------------------------------------------
__device__ __forceinline__ void lif_step(float& v0, float& v1, float& v2,
                                         float u0, float u1, float u2,
                                         bool& s0, bool& s1, bool& s2) {
    v0 = fmaf(ALPHA, v0, u0);
    v1 = fmaf(ALPHA, v1, u1);
    v2 = fmaf(ALPHA, v2, u2);
    // winner-take-all, argmax first-index tie-break, spike iff winner >= theta
    s0 = (v0 >= v1) & (v0 >= v2) & (v0 >= THETA);
    s1 = (v1 >  v0) & (v1 >= v2) & (v1 >= THETA);
    s2 = (v2 >  v0) & (v2 >  v1) & (v2 >= THETA);
    v0 = s0 ? v0 - THETA : v0;
    v1 = s1 ? v1 - THETA : v1;
    v2 = s2 ? v2 - THETA : v2;
}

__global__ void __launch_bounds__(128) scan_kernel(float* __restrict__ out_s) {
    __shared__ uint32_t sb[KK][LCH / 32][128];   // per-thread masks [k][window][b], 12 KB

    const int tid    = threadIdx.x;
    const int b0s    = (blockIdx.x & 1) * 128;
    const int c      = blockIdx.x >> 1;
    const int b      = b0s + tid;
    const int out_t0 = c * LCH;
    const int t0     = (out_t0 > WMAX) ? (out_t0 - WMAX) : 0;
    const int nw     = out_t0 - t0;      // warmup steps (0, 256, or 512)
    const int gb0    = t0 >> 2;          // starting group index

    // plane pointers in float4 units; group stride = BB float4s (4 KB)
    const float4* p0 = (const float4*)g_uB + ((size_t)0 * TT4 + gb0) * BB + b;
    const float4* p1 = (const float4*)g_uB + ((size_t)1 * TT4 + gb0) * BB + b;
    const float4* p2 = (const float4*)g_uB + ((size_t)2 * TT4 + gb0) * BB + b;

    float4 q0[G], q1[G], q2[G];
#pragma unroll
    for (int i = 0; i < G; i++) {
        q0[i] = __ldg(p0 + (size_t)i * BB);
        q1[i] = __ldg(p1 + (size_t)i * BB);
        q2[i] = __ldg(p2 + (size_t)i * BB);
    }

    float v0 = 0.f, v1 = 0.f, v2 = 0.f;
    bool s0, s1, s2;

    // ---- warmup: windows of 8 groups (32 steps) ----
    const int nww = nw >> 5;             // 0, 8, or 16 windows
    for (int ww = 0; ww < nww; ww++) {
#pragma unroll
        for (int gg = 0; gg < 8; gg++) {
            float4 a = q0[gg], bq = q1[gg], cq = q2[gg];
            q0[gg] = __ldg(p0 + (size_t)(gg + G) * BB);
            q1[gg] = __ldg(p1 + (size_t)(gg + G) * BB);
            q2[gg] = __ldg(p2 + (size_t)(gg + G) * BB);
            lif_step(v0, v1, v2, a.x, bq.x, cq.x, s0, s1, s2);
            lif_step(v0, v1, v2, a.y, bq.y, cq.y, s0, s1, s2);
            lif_step(v0, v1, v2, a.z, bq.z, cq.z, s0, s1, s2);
            lif_step(v0, v1, v2, a.w, bq.w, cq.w, s0, s1, s2);
        }
        p0 += (size_t)8 * BB; p1 += (size_t)8 * BB; p2 += (size_t)8 * BB;
    }

    // ---- main: 8 windows of 32 steps; thread-local bit packing ----
    for (int w32 = 0; w32 < LCH / 32; w32++) {
        uint32_t m0 = 0, m1 = 0, m2 = 0;
#pragma unroll
        for (int gg = 0; gg < 8; gg++) {
            float4 a = q0[gg], bq = q1[gg], cq = q2[gg];
            q0[gg] = __ldg(p0 + (size_t)(gg + G) * BB);
            q1[gg] = __ldg(p1 + (size_t)(gg + G) * BB);
            q2[gg] = __ldg(p2 + (size_t)(gg + G) * BB);
#pragma unroll
            for (int j = 0; j < 4; j++) {
                float u0 = (j == 0) ? a.x  : (j == 1) ? a.y  : (j == 2) ? a.z  : a.w;
                float u1 = (j == 0) ? bq.x : (j == 1) ? bq.y : (j == 2) ? bq.z : bq.w;
                float u2 = (j == 0) ? cq.x : (j == 1) ? cq.y : (j == 2) ? cq.z : cq.w;
                lif_step(v0, v1, v2, u0, u1, u2, s0, s1, s2);
                const uint32_t bit = 1u << (gg * 4 + j);
                if (s0) m0 |= bit;
                if (s1) m1 |= bit;
                if (s2) m2 |= bit;
            }
        }
        p0 += (size_t)8 * BB; p1 += (size_t)8 * BB; p2 += (size_t)8 * BB;
        sb[0][w32][tid] = m0;
        sb[1][w32][tid] = m1;
        sb[2][w32][tid] = m2;
    }
    __syncthreads();

    // ---- fused expansion: 128 b x 3 k x 256 t floats for this block ----
    for (int f = tid; f < 128 * 3 * (LCH / 4); f += 128) {
        int t4 = f & (LCH / 4 - 1);
        int r  = f >> 6;
        int bq = r / 3;
        int k  = r - bq * 3;
        uint32_t wv = sb[k][t4 >> 3][bq];
        int sh = (t4 & 7) * 4;
        float4 o;
        o.x = (float)((wv >> (sh + 0)) & 1u);
        o.y = (float)((wv >> (sh + 1)) & 1u);
        o.z = (float)((wv >> (sh + 2)) & 1u);
        o.w = (float)((wv >> (sh + 3)) & 1u);
        *(float4*)(out_s + ((size_t)(b0s + bq) * 3 + k) * TT + out_t0 + t4 * 4) = o;
    }
}

// ---------------------------------------------------------------------------
extern "C" void kernel_launch(void* const* d_in, const int* in_sizes, int n_in,
                              void* d_out, int out_size) {
    const float* x   = (const float*)d_in[0];
    // d_in[1] = y, unused by the reference outputs
    const float* w8  = (const float*)d_in[2];
    const float* w16 = (const float*)d_in[3];
    const float* w32 = (const float*)d_in[4];
    float* out = (float*)d_out;

    conv_kernel<<<dim3(TT / 64, BB / 32), 256>>>(x, w8, w16, w32, out);
    scan_kernel<<<NCH * 2, 128>>>(out + (size_t)BB * KK * TT);
}

// round 10
// speedup vs baseline: 1.0361x; 1.0003x over previous
#include <cuda_runtime.h>
#include <stdint.h>

#define BB 256
#define TT 32768
#define TT4 (TT / 4)
#define KK 3
#define ALPHA 0.95f
#define THETA 0.05f
#define LCH 256          // chunk length
#define NCH (TT / LCH)   // 128 chunks
#define WMAX 512         // max warmup steps
#define G 8              // float4 groups (4 steps each) in flight per plane

// scratch: u in blocked transpose [k][t/4][b][4] + pad covering the register
// pipeline's worst-case overrun (last chunk reads ~71 groups past TT4; pad=128 groups)
__device__ float g_uB[KK * TT4 * BB * 4 + 131072];

// ---------------------------------------------------------------------------
// Kernel 1: causal convs. Tile = 32 b x 64 t, 256 threads, 8 outputs/thread.
// Vectorized: phase A = 3 LDG.128 + 3 STS.128/thread; window = 10 LDS.128.
// FMA accumulation order identical to validated R3-R9 kernels (bit-identical u).
// ---------------------------------------------------------------------------
__global__ void __launch_bounds__(256) conv_kernel(const float* __restrict__ x,
                                                   const float* __restrict__ w8,
                                                   const float* __restrict__ w16,
                                                   const float* __restrict__ w32,
                                                   float* __restrict__ u_out) {
    __shared__ float wf[64];   // flipped weights: [0:32)=w32, [32:48)=w16, [48:56)=w8
    __shared__ __align__(16) float buf[KK * 32 * 69];   // 26496 B, unioned
    float (*xs)[100]    = reinterpret_cast<float (*)[100]>(buf);     // 32 x 100 = 12800 B
    float (*us)[32][69] = reinterpret_cast<float (*)[32][69]>(buf);  // 3 x 32 x 69

    const int tid    = threadIdx.x;
    const int w      = tid >> 5;
    const int l      = tid & 31;
    const int tile_t = blockIdx.x * 64;
    const int b0     = blockIdx.y * 32;

    if (tid < 32)       wf[tid] = w32[31 - tid];
    else if (tid < 48)  wf[tid] = w16[47 - tid];
    else if (tid < 56)  wf[tid] = w8[55 - tid];

    // ---- phase A (vectorized): xs[r][4*c4 .. +3] = x[b0+r][tile_t-32+4*c4 ..]
    // warp w -> rows 4w..4w+3; lane l -> (r = 4w + l/8, c4 = l%8 + 8n), n=0..2
    {
        const int r  = 4 * w + (l >> 3);
        const int c4 = l & 7;
        const float4* xrow = (const float4*)(x + (size_t)(b0 + r) * TT + tile_t - 32);
        float4* xsrow = (float4*)&xs[r][0];
        if (tile_t == 0) {
            xsrow[c4] = make_float4(0.f, 0.f, 0.f, 0.f);   // left halo = zeros
        } else {
            xsrow[c4] = xrow[c4];
        }
        xsrow[c4 + 8]  = xrow[c4 + 8];
        xsrow[c4 + 16] = xrow[c4 + 16];
    }
    __syncthreads();

    // ---- phase B: 8 outputs per thread; window via 10 LDS.128 ----
    const int bl = l;
    const int tq = w * 8;
    float win[40];                      // win[i] = x[tile_t + tq + i - 32]
    {
        const float4* wrow = (const float4*)&xs[bl][tq];   // tq % 4 == 0 -> aligned
#pragma unroll
        for (int i4 = 0; i4 < 10; i4++) {
            float4 v = wrow[i4];
            win[4 * i4 + 0] = v.x;
            win[4 * i4 + 1] = v.y;
            win[4 * i4 + 2] = v.z;
            win[4 * i4 + 3] = v.w;
        }
    }
    __syncthreads();   // xs dead; union reused as us

    float a32[8] = {0,0,0,0,0,0,0,0}, a16[8] = {0,0,0,0,0,0,0,0}, a8[8] = {0,0,0,0,0,0,0,0};
#pragma unroll
    for (int d = 0; d < 32; d++) {
        float wv = wf[d];
#pragma unroll
        for (int j = 0; j < 8; j++) a32[j] = fmaf(wv, win[32 + j - d], a32[j]);
    }
#pragma unroll
    for (int d = 0; d < 16; d++) {
        float wv = wf[32 + d];
#pragma unroll
        for (int j = 0; j < 8; j++) a16[j] = fmaf(wv, win[32 + j - d], a16[j]);
    }
#pragma unroll
    for (int d = 0; d < 8; d++) {
        float wv = wf[48 + d];
#pragma unroll
        for (int j = 0; j < 8; j++) a8[j] = fmaf(wv, win[32 + j - d], a8[j]);
    }
#pragma unroll
    for (int j = 0; j < 8; j++) {
        us[0][bl][tq + j] = a8[j];
        us[1][bl][tq + j] = a16[j];
        us[2][bl][tq + j] = a32[j];
    }
    __syncthreads();

    // ---- phase D: u_out [b][k][t] (warp writes 128B rows) ----
#pragma unroll
    for (int bbq = 0; bbq < 4; bbq++) {
        int bb = w * 4 + bbq;
        float* orow = u_out + (size_t)(b0 + bb) * 3 * TT + tile_t;
#pragma unroll
        for (int k = 0; k < 3; k++)
#pragma unroll
            for (int h = 0; h < 2; h++)
                orow[(size_t)k * TT + 32 * h + l] = us[k][bb][32 * h + l];
    }
    // ---- phase E: g_uB [k][tg][b][4] (lane = b, warp writes 512B chunks) ----
#pragma unroll
    for (int r = 0; r < 6; r++) {
        int row = w + r * 8;          // 0..47 = k*16 + tgl
        int k   = row >> 4;
        int tgl = row & 15;
        float4 v;
        v.x = us[k][l][tgl * 4 + 0];
        v.y = us[k][l][tgl * 4 + 1];
        v.z = us[k][l][tgl * 4 + 2];
        v.w = us[k][l][tgl * 4 + 3];
        *(float4*)&g_uB[(((size_t)k * TT4 + (tile_t >> 2) + tgl) * BB + b0 + l) * 4] = v;
    }
}

// ---------------------------------------------------------------------------
// Kernel 2: chunked WTA-LIF scan + fused spike expansion (unchanged from R9).
// ---------------------------------------------------------------------------
__device__ __forceinline__ void lif_step(float& v0, float& v1, float& v2,
                                         float u0, float u1, float u2,
                                         bool& s0, bool& s1, bool& s2) {
    v0 = fmaf(ALPHA, v0, u0);
    v1 = fmaf(ALPHA, v1, u1);
    v2 = fmaf(ALPHA, v2, u2);
    // winner-take-all, argmax first-index tie-break, spike iff winner >= theta
    s0 = (v0 >= v1) & (v0 >= v2) & (v0 >= THETA);
    s1 = (v1 >  v0) & (v1 >= v2) & (v1 >= THETA);
    s2 = (v2 >  v0) & (v2 >  v1) & (v2 >= THETA);
    v0 = s0 ? v0 - THETA : v0;
    v1 = s1 ? v1 - THETA : v1;
    v2 = s2 ? v2 - THETA : v2;
}

__global__ void __launch_bounds__(128) scan_kernel(float* __restrict__ out_s) {
    __shared__ uint32_t sb[KK][LCH / 32][128];   // per-thread masks [k][window][b], 12 KB

    const int tid    = threadIdx.x;
    const int b0s    = (blockIdx.x & 1) * 128;
    const int c      = blockIdx.x >> 1;
    const int b      = b0s + tid;
    const int out_t0 = c * LCH;
    const int t0     = (out_t0 > WMAX) ? (out_t0 - WMAX) : 0;
    const int nw     = out_t0 - t0;      // warmup steps (0, 256, or 512)
    const int gb0    = t0 >> 2;          // starting group index

    // plane pointers in float4 units; group stride = BB float4s (4 KB)
    const float4* p0 = (const float4*)g_uB + ((size_t)0 * TT4 + gb0) * BB + b;
    const float4* p1 = (const float4*)g_uB + ((size_t)1 * TT4 + gb0) * BB + b;
    const float4* p2 = (const float4*)g_uB + ((size_t)2 * TT4 + gb0) * BB + b;

    float4 q0[G], q1[G], q2[G];
#pragma unroll
    for (int i = 0; i < G; i++) {
        q0[i] = __ldg(p0 + (size_t)i * BB);
        q1[i] = __ldg(p1 + (size_t)i * BB);
        q2[i] = __ldg(p2 + (size_t)i * BB);
    }

    float v0 = 0.f, v1 = 0.f, v2 = 0.f;
    bool s0, s1, s2;

    // ---- warmup: windows of 8 groups (32 steps) ----
    const int nww = nw >> 5;             // 0, 8, or 16 windows
    for (int ww = 0; ww < nww; ww++) {
#pragma unroll
        for (int gg = 0; gg < 8; gg++) {
            float4 a = q0[gg], bq = q1[gg], cq = q2[gg];
            q0[gg] = __ldg(p0 + (size_t)(gg + G) * BB);
            q1[gg] = __ldg(p1 + (size_t)(gg + G) * BB);
            q2[gg] = __ldg(p2 + (size_t)(gg + G) * BB);
            lif_step(v0, v1, v2, a.x, bq.x, cq.x, s0, s1, s2);
            lif_step(v0, v1, v2, a.y, bq.y, cq.y, s0, s1, s2);
            lif_step(v0, v1, v2, a.z, bq.z, cq.z, s0, s1, s2);
            lif_step(v0, v1, v2, a.w, bq.w, cq.w, s0, s1, s2);
        }
        p0 += (size_t)8 * BB; p1 += (size_t)8 * BB; p2 += (size_t)8 * BB;
    }

    // ---- main: 8 windows of 32 steps; thread-local bit packing ----
    for (int w32 = 0; w32 < LCH / 32; w32++) {
        uint32_t m0 = 0, m1 = 0, m2 = 0;
#pragma unroll
        for (int gg = 0; gg < 8; gg++) {
            float4 a = q0[gg], bq = q1[gg], cq = q2[gg];
            q0[gg] = __ldg(p0 + (size_t)(gg + G) * BB);
            q1[gg] = __ldg(p1 + (size_t)(gg + G) * BB);
            q2[gg] = __ldg(p2 + (size_t)(gg + G) * BB);
#pragma unroll
            for (int j = 0; j < 4; j++) {
                float u0 = (j == 0) ? a.x  : (j == 1) ? a.y  : (j == 2) ? a.z  : a.w;
                float u1 = (j == 0) ? bq.x : (j == 1) ? bq.y : (j == 2) ? bq.z : bq.w;
                float u2 = (j == 0) ? cq.x : (j == 1) ? cq.y : (j == 2) ? cq.z : cq.w;
                lif_step(v0, v1, v2, u0, u1, u2, s0, s1, s2);
                const uint32_t bit = 1u << (gg * 4 + j);
                if (s0) m0 |= bit;
                if (s1) m1 |= bit;
                if (s2) m2 |= bit;
            }
        }
        p0 += (size_t)8 * BB; p1 += (size_t)8 * BB; p2 += (size_t)8 * BB;
        sb[0][w32][tid] = m0;
        sb[1][w32][tid] = m1;
        sb[2][w32][tid] = m2;
    }
    __syncthreads();

    // ---- fused expansion: 128 b x 3 k x 256 t floats for this block ----
    for (int f = tid; f < 128 * 3 * (LCH / 4); f += 128) {
        int t4 = f & (LCH / 4 - 1);
        int r  = f >> 6;
        int bq = r / 3;
        int k  = r - bq * 3;
        uint32_t wv = sb[k][t4 >> 3][bq];
        int sh = (t4 & 7) * 4;
        float4 o;
        o.x = (float)((wv >> (sh + 0)) & 1u);
        o.y = (float)((wv >> (sh + 1)) & 1u);
        o.z = (float)((wv >> (sh + 2)) & 1u);
        o.w = (float)((wv >> (sh + 3)) & 1u);
        *(float4*)(out_s + ((size_t)(b0s + bq) * 3 + k) * TT + out_t0 + t4 * 4) = o;
    }
}

// ---------------------------------------------------------------------------
extern "C" void kernel_launch(void* const* d_in, const int* in_sizes, int n_in,
                              void* d_out, int out_size) {
    const float* x   = (const float*)d_in[0];
    // d_in[1] = y, unused by the reference outputs
    const float* w8  = (const float*)d_in[2];
    const float* w16 = (const float*)d_in[3];
    const float* w32 = (const float*)d_in[4];
    float* out = (float*)d_out;

    conv_kernel<<<dim3(TT / 64, BB / 32), 256>>>(x, w8, w16, w32, out);
    scan_kernel<<<NCH * 2, 128>>>(out + (size_t)BB * KK * TT);
}